// round 14
// baseline (speedup 1.0000x reference)
#include <cuda_runtime.h>
#include <cstdint>

#define NQ     4
#define IMG    576
#define TPB    256
#define SPR    4                 // samples per round
#define NBUF   4                 // ring depth
#define SS     584               // padded sample stride in smem floats
#define BUFB   (SPR * SS * 4)    // bytes per stage buffer
#define NBLK   592               // 148 SMs x 4 blocks, all co-resident
#define BN_EPS 1e-5f

// static scratch (no allocation)
__device__ float g_partials[NBLK * 8];
__device__ float g_scale[4];
__device__ float g_shift[4];
__device__ unsigned int g_ticket  = 0;   // monotonic across graph replays
__device__ unsigned int g_release = 0;   // monotonic across graph replays

__device__ __forceinline__ void cp_async16(uint32_t smem_addr, const void* gptr) {
    asm volatile("cp.async.cg.shared.global [%0], [%1], 16;\n" :: "r"(smem_addr), "l"(gptr));
}
#define CP_COMMIT() asm volatile("cp.async.commit_group;\n" ::: "memory")
#define CP_WAIT2()  asm volatile("cp.async.wait_group 2;\n" ::: "memory")

__device__ __forceinline__ uint32_t stage_off(int i4) {
    int s = i4 / 144, w = i4 - s * 144;
    return (uint32_t)(s * SS + w * 4) * 4u;
}

// ---------------- single fused kernel ----------------
__global__ void __launch_bounds__(TPB, 4) k_main(
    const float* __restrict__ x,
    const float* __restrict__ enc_w,   // (4,16)
    const float* __restrict__ enc_b,   // (4,)
    const float* __restrict__ qp,      // (2,4)
    const float* __restrict__ bnw,
    const float* __restrict__ bnb,
    float* __restrict__ zout,          // (B,4)
    int R_total, int B)
{
    __shared__ float stage[NBUF][SPR * SS];   // 4 x 9344 B
    __shared__ float pr[NBUF][SPR][17];
    __shared__ float sred[8][8];
    __shared__ unsigned int s_epoch;
    __shared__ int s_last;

    const int t    = threadIdx.x;
    const int blk  = blockIdx.x;
    const int nblk = gridDim.x;

    const int r0 = (int)((long long)blk * R_total / nblk);
    const int r1 = (int)((long long)(blk + 1) * R_total / nblk);
    const int n  = r1 - r0;                       // ~55-56

    const float4* xg = (const float4*)(x + (size_t)r0 * SPR * IMG);
    const uint32_t sb = (uint32_t)__cvta_generic_to_shared(&stage[0][0]);

    // round-invariant staging offsets (576 float4 per round)
    const int i4a = t, i4b = t + 256;
    const uint32_t offa = stage_off(i4a);
    const uint32_t offb = stage_off(i4b);
    const bool hasC = (t < 64);
    const uint32_t offc = hasC ? stage_off(t + 512) : 0u;

    float enc[NQ];
#pragma unroll
    for (int k = 0; k < NQ; k++) enc[k] = __ldg(enc_b + k);

    // prologue: issue rounds 0..2
#pragma unroll
    for (int j = 0; j < 3; j++) {
        if (j < n) {
            const float4* src = xg + (size_t)j * 576;
            uint32_t base = sb + (uint32_t)(j & 3) * BUFB;
            cp_async16(base + offa, src + i4a);
            cp_async16(base + offb, src + i4b);
            if (hasC) cp_async16(base + offc, src + (t + 512));
        }
        CP_COMMIT();
    }

#pragma unroll 1
    for (int r = 0; r < n; r++) {
        CP_WAIT2();
        __syncthreads();

        // refill round r+3 into freed buffer
        if (r + 3 < n) {
            const float4* src = xg + (size_t)(r + 3) * 576;
            uint32_t base = sb + (uint32_t)((r + 3) & 3) * BUFB;
            cp_async16(base + offa, src + i4a);
            cp_async16(base + offb, src + i4b);
            if (hasC) cp_async16(base + offc, src + (t + 512));
        }
        CP_COMMIT();

        // pool round r: rotating 2-warp duty
        {
            int tp = t - ((r & 3) << 6);
            if ((unsigned)tp < 64u) {
                int s  = tp >> 4, b = tp & 15;
                int rb = b >> 2, cb = b & 3;
                const float* bp = &stage[r & 3][0] + s * SS + rb * 144 + cb * 6;
                float acc = 0.f;
#pragma unroll
                for (int dr = 0; dr < 6; dr++) {
                    const float2* p2 = (const float2*)(bp + dr * 24);
                    float2 a = p2[0], c = p2[1], d = p2[2];
                    acc += (a.x + a.y) + (c.x + c.y) + (d.x + d.y);
                }
                pr[r & 3][s][b] = acc * (1.0f / 36.0f);
            }
        }

        // owners of round r-1 fold pooled -> enc
        if (r > 0 && (t >> 2) == r - 1) {
            const float* pv = pr[(r - 1) & 3][t & 3];
#pragma unroll
            for (int k = 0; k < NQ; k++) {
                float a = enc[k];
#pragma unroll
                for (int i = 0; i < 16; i++)
                    a += pv[i] * __ldg(enc_w + k * 16 + i);
                enc[k] = a;
            }
        }
    }

    // drain: fold last round
    __syncthreads();
    if ((t >> 2) == n - 1) {
        const float* pv = pr[(n - 1) & 3][t & 3];
#pragma unroll
        for (int k = 0; k < NQ; k++) {
            float a = enc[k];
#pragma unroll
            for (int i = 0; i < 16; i++)
                a += pv[i] * __ldg(enc_w + k * 16 + i);
            enc[k] = a;
        }
    }

    const bool active = t < 4 * n;

    // ---- statevector circuit in registers ----
    float sx[16], sy[16];
#pragma unroll
    for (int i = 0; i < 16; i++) { sx[i] = 0.f; sy[i] = 0.f; }
    sx[0] = 1.f;

#pragma unroll
    for (int layer = 0; layer < 2; layer++) {
#pragma unroll
        for (int q = 0; q < NQ; q++) {
            const int st = 8 >> q;
            float c, sn;
            __sincosf(0.5f * enc[q], &sn, &c);
#pragma unroll
            for (int i = 0; i < 16; i++) {
                if ((i & st) == 0) {
                    const int j = i | st;
                    float ax = sx[i], ay = sy[i];
                    float bx = sx[j], by = sy[j];
                    sx[i] = c * ax - sn * bx;  sy[i] = c * ay - sn * by;
                    sx[j] = sn * ax + c * bx;  sy[j] = sn * ay + c * by;
                }
            }
            float hc, hs;
            __sincosf(0.5f * __ldg(qp + layer * NQ + q), &hs, &hc);
#pragma unroll
            for (int i = 0; i < 16; i++) {
                float xx = sx[i], yy = sy[i];
                if (i & st) { sx[i] = xx * hc - yy * hs;  sy[i] = yy * hc + xx * hs; }
                else        { sx[i] = xx * hc + yy * hs;  sy[i] = yy * hc - xx * hs; }
            }
        }
        {   // composed CNOT ring permutation
            constexpr int P[16] = {0, 13, 3, 14, 6, 11, 5, 8, 12, 1, 15, 2, 10, 7, 9, 4};
            float tx[16], ty[16];
#pragma unroll
            for (int i = 0; i < 16; i++) { tx[i] = sx[i]; ty[i] = sy[i]; }
#pragma unroll
            for (int i = 0; i < 16; i++) { sx[i] = tx[P[i]]; sy[i] = ty[P[i]]; }
        }
    }

    // ---- Z expectations (masked) ----
    float z0 = 0.f, z1 = 0.f, z2 = 0.f, z3 = 0.f;
    if (active) {
#pragma unroll
        for (int i = 0; i < 16; i++) {
            float p2 = sx[i] * sx[i] + sy[i] * sy[i];
            z0 += ((i >> 3) & 1) ? -p2 : p2;
            z1 += ((i >> 2) & 1) ? -p2 : p2;
            z2 += ((i >> 1) & 1) ? -p2 : p2;
            z3 += ( i       & 1) ? -p2 : p2;
        }
    }

    // ---- deterministic block (sum, sumsq) ----
    {
        float v[8] = {z0, z1, z2, z3, z0 * z0, z1 * z1, z2 * z2, z3 * z3};
#pragma unroll
        for (int off = 16; off >= 1; off >>= 1)
#pragma unroll
            for (int j = 0; j < 8; j++)
                v[j] += __shfl_xor_sync(0xffffffffu, v[j], off);

        const int wid = t >> 5, lid = t & 31;
        if (lid == 0)
#pragma unroll
            for (int j = 0; j < 8; j++) sred[wid][j] = v[j];
        __syncthreads();
        if (t < 8) {
            float a = 0.f;
#pragma unroll
            for (int w = 0; w < 8; w++) a += sred[w][t];
            g_partials[(size_t)blk * 8 + t] = a;
        }
    }

    // ---- ticket: detect last-arriving block, establish epoch ----
    if (t == 0) {
        __threadfence();                                   // publish partials
        unsigned int old = atomicAdd(&g_ticket, 1u);
        unsigned int e   = old / (unsigned)nblk;           // replay epoch
        s_epoch = e;
        s_last  = (old == (e + 1u) * (unsigned)nblk - 1u) ? 1 : 0;
    }
    __syncthreads();
    const unsigned int target = s_epoch + 1u;

    if (s_last) {
        __threadfence();                                   // acquire all partials
        __shared__ float s2[256];
        const int stat = t & 7;
        const int g    = t >> 3;
        float acc = 0.f;
        for (int i = g; i < nblk; i += 32)
            acc += g_partials[(size_t)i * 8 + stat];
        s2[t] = acc;
        __syncthreads();
#pragma unroll
        for (int off = 128; off >= 8; off >>= 1) {
            if (t < off) s2[t] += s2[t + off];
            __syncthreads();
        }
        if (t < 4) {
            float invB = 1.0f / (float)B;
            float mean = s2[t] * invB;
            float var  = s2[4 + t] * invB - mean * mean;
            float inv  = rsqrtf(var + BN_EPS);
            float sc   = inv * __ldg(bnw + t);
            g_scale[t] = sc;
            g_shift[t] = __ldg(bnb + t) - mean * sc;
        }
        __syncthreads();
        if (t == 0) {
            __threadfence();                               // scale/shift visible
            asm volatile("st.global.release.gpu.u32 [%0], %1;"
                         :: "l"(&g_release), "r"(target) : "memory");
        }
    }

    // ---- contention-free wait: plain acquire loads + backoff ----
    if (t == 0) {
        unsigned int v;
        while (true) {
            asm volatile("ld.global.acquire.gpu.u32 %0, [%1];"
                         : "=r"(v) : "l"(&g_release) : "memory");
            if (v >= target) break;
            __nanosleep(200);
        }
    }
    __syncthreads();

    // ---- normalize in registers, single store ----
    if (active) {
        float4 z;
        z.x = z0 * g_scale[0] + g_shift[0];
        z.y = z1 * g_scale[1] + g_shift[1];
        z.z = z2 * g_scale[2] + g_shift[2];
        z.w = z3 * g_scale[3] + g_shift[3];
        *(float4*)(zout + ((size_t)r0 * SPR + t) * 4) = z;
    }
}

extern "C" void kernel_launch(void* const* d_in, const int* in_sizes, int n_in,
                              void* d_out, int out_size)
{
    const float* x     = (const float*)d_in[0];
    const float* enc_w = (const float*)d_in[1];
    const float* enc_b = (const float*)d_in[2];
    const float* qp    = (const float*)d_in[3];
    const float* bnw   = (const float*)d_in[4];
    const float* bnb   = (const float*)d_in[5];
    float* out = (float*)d_out;

    int B       = in_sizes[0] / IMG;   // 131072
    int R_total = B / SPR;             // 32768

    k_main<<<NBLK, TPB>>>(x, enc_w, enc_b, qp, bnw, bnb, out, R_total, B);
}

// round 15
// speedup vs baseline: 1.0721x; 1.0721x over previous
#include <cuda_runtime.h>
#include <cstdint>

#define NQ     4
#define IMG    576
#define TPB    256
#define SPR    4                 // samples per round
#define NBUF   4                 // ring depth
#define SS     584               // padded sample stride in smem floats
#define BUFB   (SPR * SS * 4)    // bytes per stage buffer
#define NBLK   592               // 148 SMs x 4 blocks
#define BN_EPS 1e-5f

// static scratch (no allocation)
__device__ float g_partials[NBLK * 8];

__device__ __forceinline__ void cp_async16(uint32_t smem_addr, const void* gptr) {
    asm volatile("cp.async.cg.shared.global [%0], [%1], 16;\n" :: "r"(smem_addr), "l"(gptr));
}
#define CP_COMMIT() asm volatile("cp.async.commit_group;\n" ::: "memory")
#define CP_WAIT2()  asm volatile("cp.async.wait_group 2;\n" ::: "memory")

__device__ __forceinline__ uint32_t stage_off(int i4) {
    int s = i4 / 144, w = i4 - s * 144;
    return (uint32_t)(s * SS + w * 4) * 4u;
}

// ---------------- fused pool + circuit + partial-stats (R7 core, unchanged) ----------------
__global__ void __launch_bounds__(TPB, 4) k_main(
    const float* __restrict__ x,
    const float* __restrict__ enc_w,   // (4,16)
    const float* __restrict__ enc_b,   // (4,)
    const float* __restrict__ qp,      // (2,4)
    float* __restrict__ zout,          // (B,4)
    int R_total)
{
    __shared__ float stage[NBUF][SPR * SS];   // 4 x 9344 B
    __shared__ float pr[NBUF][SPR][17];
    __shared__ float sred[8][8];

    const int t    = threadIdx.x;
    const int blk  = blockIdx.x;
    const int nblk = gridDim.x;

    const int r0 = (int)((long long)blk * R_total / nblk);
    const int r1 = (int)((long long)(blk + 1) * R_total / nblk);
    const int n  = r1 - r0;                       // ~55-56

    const float4* xg = (const float4*)(x + (size_t)r0 * SPR * IMG);
    const uint32_t sb = (uint32_t)__cvta_generic_to_shared(&stage[0][0]);

    // round-invariant staging offsets (576 float4 per round)
    const int i4a = t, i4b = t + 256;
    const uint32_t offa = stage_off(i4a);
    const uint32_t offb = stage_off(i4b);
    const bool hasC = (t < 64);
    const uint32_t offc = hasC ? stage_off(t + 512) : 0u;

    float enc[NQ];
#pragma unroll
    for (int k = 0; k < NQ; k++) enc[k] = __ldg(enc_b + k);

    // prologue: issue rounds 0..2
#pragma unroll
    for (int j = 0; j < 3; j++) {
        if (j < n) {
            const float4* src = xg + (size_t)j * 576;
            uint32_t base = sb + (uint32_t)(j & 3) * BUFB;
            cp_async16(base + offa, src + i4a);
            cp_async16(base + offb, src + i4b);
            if (hasC) cp_async16(base + offc, src + (t + 512));
        }
        CP_COMMIT();
    }

#pragma unroll 1
    for (int r = 0; r < n; r++) {
        CP_WAIT2();
        __syncthreads();

        // refill round r+3 into freed buffer
        if (r + 3 < n) {
            const float4* src = xg + (size_t)(r + 3) * 576;
            uint32_t base = sb + (uint32_t)((r + 3) & 3) * BUFB;
            cp_async16(base + offa, src + i4a);
            cp_async16(base + offb, src + i4b);
            if (hasC) cp_async16(base + offc, src + (t + 512));
        }
        CP_COMMIT();

        // pool round r: rotating 2-warp duty
        {
            int tp = t - ((r & 3) << 6);
            if ((unsigned)tp < 64u) {
                int s  = tp >> 4, b = tp & 15;
                int rb = b >> 2, cb = b & 3;
                const float* bp = &stage[r & 3][0] + s * SS + rb * 144 + cb * 6;
                float acc = 0.f;
#pragma unroll
                for (int dr = 0; dr < 6; dr++) {
                    const float2* p2 = (const float2*)(bp + dr * 24);
                    float2 a = p2[0], c = p2[1], d = p2[2];
                    acc += (a.x + a.y) + (c.x + c.y) + (d.x + d.y);
                }
                pr[r & 3][s][b] = acc * (1.0f / 36.0f);
            }
        }

        // owners of round r-1 fold pooled -> enc
        if (r > 0 && (t >> 2) == r - 1) {
            const float* pv = pr[(r - 1) & 3][t & 3];
#pragma unroll
            for (int k = 0; k < NQ; k++) {
                float a = enc[k];
#pragma unroll
                for (int i = 0; i < 16; i++)
                    a += pv[i] * __ldg(enc_w + k * 16 + i);
                enc[k] = a;
            }
        }
    }

    // drain: fold last round
    __syncthreads();
    if ((t >> 2) == n - 1) {
        const float* pv = pr[(n - 1) & 3][t & 3];
#pragma unroll
        for (int k = 0; k < NQ; k++) {
            float a = enc[k];
#pragma unroll
            for (int i = 0; i < 16; i++)
                a += pv[i] * __ldg(enc_w + k * 16 + i);
            enc[k] = a;
        }
    }

    const bool active = t < 4 * n;

    // ---- statevector circuit in registers ----
    float sx[16], sy[16];
#pragma unroll
    for (int i = 0; i < 16; i++) { sx[i] = 0.f; sy[i] = 0.f; }
    sx[0] = 1.f;

#pragma unroll
    for (int layer = 0; layer < 2; layer++) {
#pragma unroll
        for (int q = 0; q < NQ; q++) {
            const int st = 8 >> q;
            float c, sn;
            __sincosf(0.5f * enc[q], &sn, &c);
#pragma unroll
            for (int i = 0; i < 16; i++) {
                if ((i & st) == 0) {
                    const int j = i | st;
                    float ax = sx[i], ay = sy[i];
                    float bx = sx[j], by = sy[j];
                    sx[i] = c * ax - sn * bx;  sy[i] = c * ay - sn * by;
                    sx[j] = sn * ax + c * bx;  sy[j] = sn * ay + c * by;
                }
            }
            float hc, hs;
            __sincosf(0.5f * __ldg(qp + layer * NQ + q), &hs, &hc);
#pragma unroll
            for (int i = 0; i < 16; i++) {
                float xx = sx[i], yy = sy[i];
                if (i & st) { sx[i] = xx * hc - yy * hs;  sy[i] = yy * hc + xx * hs; }
                else        { sx[i] = xx * hc + yy * hs;  sy[i] = yy * hc - xx * hs; }
            }
        }
        {   // composed CNOT ring permutation
            constexpr int P[16] = {0, 13, 3, 14, 6, 11, 5, 8, 12, 1, 15, 2, 10, 7, 9, 4};
            float tx[16], ty[16];
#pragma unroll
            for (int i = 0; i < 16; i++) { tx[i] = sx[i]; ty[i] = sy[i]; }
#pragma unroll
            for (int i = 0; i < 16; i++) { sx[i] = tx[P[i]]; sy[i] = ty[P[i]]; }
        }
    }

    // ---- Z expectations (masked) + store raw z ----
    float z0 = 0.f, z1 = 0.f, z2 = 0.f, z3 = 0.f;
    if (active) {
#pragma unroll
        for (int i = 0; i < 16; i++) {
            float p2 = sx[i] * sx[i] + sy[i] * sy[i];
            z0 += ((i >> 3) & 1) ? -p2 : p2;
            z1 += ((i >> 2) & 1) ? -p2 : p2;
            z2 += ((i >> 1) & 1) ? -p2 : p2;
            z3 += ( i       & 1) ? -p2 : p2;
        }
        *(float4*)(zout + ((size_t)r0 * SPR + t) * 4) = make_float4(z0, z1, z2, z3);
    }

    // ---- deterministic block (sum, sumsq) ----
    float v[8] = {z0, z1, z2, z3, z0 * z0, z1 * z1, z2 * z2, z3 * z3};
#pragma unroll
    for (int off = 16; off >= 1; off >>= 1)
#pragma unroll
        for (int j = 0; j < 8; j++)
            v[j] += __shfl_xor_sync(0xffffffffu, v[j], off);

    const int wid = t >> 5, lid = t & 31;
    if (lid == 0)
#pragma unroll
        for (int j = 0; j < 8; j++) sred[wid][j] = v[j];
    __syncthreads();
    if (t < 8) {
        float a = 0.f;
#pragma unroll
        for (int w = 0; w < 8; w++) a += sred[w][t];
        g_partials[(size_t)blk * 8 + t] = a;
    }
}

// ---------------- k_finish: redundant stats + normalize, ONE launch ----------------
__global__ void __launch_bounds__(256) k_finish(
    const float* __restrict__ bnw,
    const float* __restrict__ bnb,
    float* __restrict__ zout,
    int nblk, int B)
{
    __shared__ float s2[256];
    __shared__ float sc4[4], sh4[4];

    const int t = threadIdx.x;

    // Phase 1: every block redundantly reduces the partials (deterministic
    // identical order in all blocks -> identical scale/shift everywhere).
    {
        const int stat = t & 7;
        const int g    = t >> 3;   // 32 groups per stat
        float acc = 0.f;
        for (int i = g; i < nblk; i += 32)
            acc += g_partials[(size_t)i * 8 + stat];
        s2[t] = acc;
    }
    __syncthreads();
#pragma unroll
    for (int off = 128; off >= 8; off >>= 1) {
        if (t < off) s2[t] += s2[t + off];
        __syncthreads();
    }
    if (t < 4) {
        float invB = 1.0f / (float)B;
        float mean = s2[t] * invB;
        float var  = s2[4 + t] * invB - mean * mean;
        float inv  = rsqrtf(var + BN_EPS);
        float sc   = inv * __ldg(bnw + t);
        sc4[t] = sc;
        sh4[t] = __ldg(bnb + t) - mean * sc;
    }
    __syncthreads();

    const float4 sc = make_float4(sc4[0], sc4[1], sc4[2], sc4[3]);
    const float4 sh = make_float4(sh4[0], sh4[1], sh4[2], sh4[3]);

    // Phase 2: normalize (4 independent float4 per thread)
    const int base   = blockIdx.x * 256 + t;
    const int stride = gridDim.x * 256;
    const int n4     = B;

    float4 v[4];
    int idx[4];
#pragma unroll
    for (int k = 0; k < 4; k++) {
        idx[k] = base + k * stride;
        if (idx[k] < n4) v[k] = ((float4*)zout)[idx[k]];
    }
#pragma unroll
    for (int k = 0; k < 4; k++) {
        if (idx[k] < n4) {
            float4 z = v[k];
            z.x = z.x * sc.x + sh.x;
            z.y = z.y * sc.y + sh.y;
            z.z = z.z * sc.z + sh.z;
            z.w = z.w * sc.w + sh.w;
            ((float4*)zout)[idx[k]] = z;
        }
    }
}

extern "C" void kernel_launch(void* const* d_in, const int* in_sizes, int n_in,
                              void* d_out, int out_size)
{
    const float* x     = (const float*)d_in[0];
    const float* enc_w = (const float*)d_in[1];
    const float* enc_b = (const float*)d_in[2];
    const float* qp    = (const float*)d_in[3];
    const float* bnw   = (const float*)d_in[4];
    const float* bnb   = (const float*)d_in[5];
    float* out = (float*)d_out;

    int B       = in_sizes[0] / IMG;   // 131072
    int R_total = B / SPR;             // 32768

    k_main<<<NBLK, TPB>>>(x, enc_w, enc_b, qp, out, R_total);
    k_finish<<<128, 256>>>(bnw, bnb, out, NBLK, B);
}